// round 4
// baseline (speedup 1.0000x reference)
#include <cuda_runtime.h>
#include <cstddef>

// SNN: 2-2-2 spiking net, B=500k independent batch elements, T=32 steps.
// R3 passed at 57.8us (DRAM 70.9%, L1 66%). This revision processes TWO
// batch elements per thread so every output store is a 16B STG.128,
// halving store-instruction count and L1 wavefront pressure.
//
// FP association mirrors XLA's lowering exactly (verified rel_err==0):
//   dot:  acc = fma(x1, w[j][1], rnd(x0 * w[j][0]))
//   bias: cur = acc + b[j]
//   mem:  ((beta*mem + cur) - reset)   with separate rn ops
//
// Output layout: [spk1 | spk2 | mem2], each [T,B,2] float32.

template<int T_STEPS>
__global__ __launch_bounds__(256)
void snn_kernel2(const float4* __restrict__ x,      // pairs: {x[2p], x[2p+1]}
                 const float* __restrict__ fc1_w, const float* __restrict__ fc1_b,
                 const float* __restrict__ beta1, const float* __restrict__ thr1,
                 const float* __restrict__ fc2_w, const float* __restrict__ fc2_b,
                 const float* __restrict__ beta2, const float* __restrict__ thr2,
                 float4* __restrict__ out,          // pair-granular view
                 int Bp,                            // B/2 pairs
                 int T_dyn)
{
    const int p = blockIdx.x * blockDim.x + threadIdx.x;
    if (p >= Bp) return;

    const float w1_00 = __ldg(fc1_w + 0), w1_01 = __ldg(fc1_w + 1);
    const float w1_10 = __ldg(fc1_w + 2), w1_11 = __ldg(fc1_w + 3);
    const float b1_0  = __ldg(fc1_b + 0), b1_1  = __ldg(fc1_b + 1);
    const float w2_00 = __ldg(fc2_w + 0), w2_01 = __ldg(fc2_w + 1);
    const float w2_10 = __ldg(fc2_w + 2), w2_11 = __ldg(fc2_w + 3);
    const float b2_0  = __ldg(fc2_b + 0), b2_1  = __ldg(fc2_b + 1);
    const float bt1   = fminf(fmaxf(__ldg(beta1), 0.f), 1.f);
    const float bt2   = fminf(fmaxf(__ldg(beta2), 0.f), 1.f);
    const float th1   = __ldg(thr1);
    const float th2   = __ldg(thr2);

    const float4 xv = __ldg(&x[p]);   // elem A = (x,y), elem B = (z,w)

    // Time-invariant layer-1 currents for both elements.
    const float c1A0 = __fadd_rn(__fmaf_rn(xv.y, w1_01, __fmul_rn(xv.x, w1_00)), b1_0);
    const float c1A1 = __fadd_rn(__fmaf_rn(xv.y, w1_11, __fmul_rn(xv.x, w1_10)), b1_1);
    const float c1B0 = __fadd_rn(__fmaf_rn(xv.w, w1_01, __fmul_rn(xv.z, w1_00)), b1_0);
    const float c1B1 = __fadd_rn(__fmaf_rn(xv.w, w1_11, __fmul_rn(xv.z, w1_10)), b1_1);

    float m1A0 = 0.f, m1A1 = 0.f, m1B0 = 0.f, m1B1 = 0.f;
    float m2A0 = 0.f, m2A1 = 0.f, m2B0 = 0.f, m2B1 = 0.f;

    const int T = (T_STEPS > 0) ? T_STEPS : T_dyn;
    // out viewed as float4 with pair granularity: each [T,B,2] array holds
    // T*Bp float4 rows.
    const size_t TBp = (size_t)T * (size_t)Bp;
    float4* __restrict__ o_spk1 = out;
    float4* __restrict__ o_spk2 = out + TBp;
    float4* __restrict__ o_mem2 = out + 2 * TBp;

#pragma unroll
    for (int t = 0; t < T; t++) {
        // ---- layer 1 ----
        const float r1A0 = (m1A0 > th1) ? th1 : 0.f;
        const float r1A1 = (m1A1 > th1) ? th1 : 0.f;
        const float r1B0 = (m1B0 > th1) ? th1 : 0.f;
        const float r1B1 = (m1B1 > th1) ? th1 : 0.f;
        m1A0 = __fsub_rn(__fadd_rn(__fmul_rn(bt1, m1A0), c1A0), r1A0);
        m1A1 = __fsub_rn(__fadd_rn(__fmul_rn(bt1, m1A1), c1A1), r1A1);
        m1B0 = __fsub_rn(__fadd_rn(__fmul_rn(bt1, m1B0), c1B0), r1B0);
        m1B1 = __fsub_rn(__fadd_rn(__fmul_rn(bt1, m1B1), c1B1), r1B1);
        const float s1A0 = (m1A0 > th1) ? 1.f : 0.f;
        const float s1A1 = (m1A1 > th1) ? 1.f : 0.f;
        const float s1B0 = (m1B0 > th1) ? 1.f : 0.f;
        const float s1B1 = (m1B1 > th1) ? 1.f : 0.f;

        // ---- layer 2 currents ----
        const float c2A0 = __fadd_rn(__fmaf_rn(s1A1, w2_01, __fmul_rn(s1A0, w2_00)), b2_0);
        const float c2A1 = __fadd_rn(__fmaf_rn(s1A1, w2_11, __fmul_rn(s1A0, w2_10)), b2_1);
        const float c2B0 = __fadd_rn(__fmaf_rn(s1B1, w2_01, __fmul_rn(s1B0, w2_00)), b2_0);
        const float c2B1 = __fadd_rn(__fmaf_rn(s1B1, w2_11, __fmul_rn(s1B0, w2_10)), b2_1);

        // ---- layer 2 ----
        const float r2A0 = (m2A0 > th2) ? th2 : 0.f;
        const float r2A1 = (m2A1 > th2) ? th2 : 0.f;
        const float r2B0 = (m2B0 > th2) ? th2 : 0.f;
        const float r2B1 = (m2B1 > th2) ? th2 : 0.f;
        m2A0 = __fsub_rn(__fadd_rn(__fmul_rn(bt2, m2A0), c2A0), r2A0);
        m2A1 = __fsub_rn(__fadd_rn(__fmul_rn(bt2, m2A1), c2A1), r2A1);
        m2B0 = __fsub_rn(__fadd_rn(__fmul_rn(bt2, m2B0), c2B0), r2B0);
        m2B1 = __fsub_rn(__fadd_rn(__fmul_rn(bt2, m2B1), c2B1), r2B1);
        const float s2A0 = (m2A0 > th2) ? 1.f : 0.f;
        const float s2A1 = (m2A1 > th2) ? 1.f : 0.f;
        const float s2B0 = (m2B0 > th2) ? 1.f : 0.f;
        const float s2B1 = (m2B1 > th2) ? 1.f : 0.f;

        const size_t idx = (size_t)t * (size_t)Bp + (size_t)p;
        __stcs(&o_spk1[idx], make_float4(s1A0, s1A1, s1B0, s1B1));
        __stcs(&o_spk2[idx], make_float4(s2A0, s2A1, s2B0, s2B1));
        __stcs(&o_mem2[idx], make_float4(m2A0, m2A1, m2B0, m2B1));
    }
}

// Fallback for odd B (one element per thread, float2 stores).
__global__ __launch_bounds__(256)
void snn_kernel1(const float2* __restrict__ x,
                 const float* __restrict__ fc1_w, const float* __restrict__ fc1_b,
                 const float* __restrict__ beta1, const float* __restrict__ thr1,
                 const float* __restrict__ fc2_w, const float* __restrict__ fc2_b,
                 const float* __restrict__ beta2, const float* __restrict__ thr2,
                 float2* __restrict__ out, int B, int T)
{
    const int b = blockIdx.x * blockDim.x + threadIdx.x;
    if (b >= B) return;

    const float w1_00 = __ldg(fc1_w + 0), w1_01 = __ldg(fc1_w + 1);
    const float w1_10 = __ldg(fc1_w + 2), w1_11 = __ldg(fc1_w + 3);
    const float b1_0  = __ldg(fc1_b + 0), b1_1  = __ldg(fc1_b + 1);
    const float w2_00 = __ldg(fc2_w + 0), w2_01 = __ldg(fc2_w + 1);
    const float w2_10 = __ldg(fc2_w + 2), w2_11 = __ldg(fc2_w + 3);
    const float b2_0  = __ldg(fc2_b + 0), b2_1  = __ldg(fc2_b + 1);
    const float bt1   = fminf(fmaxf(__ldg(beta1), 0.f), 1.f);
    const float bt2   = fminf(fmaxf(__ldg(beta2), 0.f), 1.f);
    const float th1   = __ldg(thr1);
    const float th2   = __ldg(thr2);

    const float2 xv = __ldg(&x[b]);
    const float cur1_0 = __fadd_rn(__fmaf_rn(xv.y, w1_01, __fmul_rn(xv.x, w1_00)), b1_0);
    const float cur1_1 = __fadd_rn(__fmaf_rn(xv.y, w1_11, __fmul_rn(xv.x, w1_10)), b1_1);

    float mem1_0 = 0.f, mem1_1 = 0.f, mem2_0 = 0.f, mem2_1 = 0.f;
    const size_t TB = (size_t)T * (size_t)B;
    float2* __restrict__ o_spk1 = out;
    float2* __restrict__ o_spk2 = out + TB;
    float2* __restrict__ o_mem2 = out + 2 * TB;

    for (int t = 0; t < T; t++) {
        const float r1_0 = (mem1_0 > th1) ? th1 : 0.f;
        const float r1_1 = (mem1_1 > th1) ? th1 : 0.f;
        mem1_0 = __fsub_rn(__fadd_rn(__fmul_rn(bt1, mem1_0), cur1_0), r1_0);
        mem1_1 = __fsub_rn(__fadd_rn(__fmul_rn(bt1, mem1_1), cur1_1), r1_1);
        const float s1_0 = (mem1_0 > th1) ? 1.f : 0.f;
        const float s1_1 = (mem1_1 > th1) ? 1.f : 0.f;
        const float cur2_0 = __fadd_rn(__fmaf_rn(s1_1, w2_01, __fmul_rn(s1_0, w2_00)), b2_0);
        const float cur2_1 = __fadd_rn(__fmaf_rn(s1_1, w2_11, __fmul_rn(s1_0, w2_10)), b2_1);
        const float r2_0 = (mem2_0 > th2) ? th2 : 0.f;
        const float r2_1 = (mem2_1 > th2) ? th2 : 0.f;
        mem2_0 = __fsub_rn(__fadd_rn(__fmul_rn(bt2, mem2_0), cur2_0), r2_0);
        mem2_1 = __fsub_rn(__fadd_rn(__fmul_rn(bt2, mem2_1), cur2_1), r2_1);
        const float s2_0 = (mem2_0 > th2) ? 1.f : 0.f;
        const float s2_1 = (mem2_1 > th2) ? 1.f : 0.f;

        const size_t idx = (size_t)t * (size_t)B + (size_t)b;
        __stcs(&o_spk1[idx], make_float2(s1_0, s1_1));
        __stcs(&o_spk2[idx], make_float2(s2_0, s2_1));
        __stcs(&o_mem2[idx], make_float2(mem2_0, mem2_1));
    }
}

extern "C" void kernel_launch(void* const* d_in, const int* in_sizes, int n_in,
                              void* d_out, int out_size) {
    const float*  fc1_w = (const float*)d_in[1];
    const float*  fc1_b = (const float*)d_in[2];
    const float*  beta1 = (const float*)d_in[3];
    const float*  thr1  = (const float*)d_in[4];
    const float*  fc2_w = (const float*)d_in[5];
    const float*  fc2_b = (const float*)d_in[6];
    const float*  beta2 = (const float*)d_in[7];
    const float*  thr2  = (const float*)d_in[8];

    const int B = in_sizes[0] / 2;          // x is [B, 2]
    const int T = out_size / (6 * B);       // out = 3 arrays of [T, B, 2]

    const int threads = 256;

    if ((B & 1) == 0) {
        const int Bp = B / 2;
        const int blocks = (Bp + threads - 1) / threads;
        if (T == 32) {
            snn_kernel2<32><<<blocks, threads>>>((const float4*)d_in[0],
                fc1_w, fc1_b, beta1, thr1, fc2_w, fc2_b, beta2, thr2,
                (float4*)d_out, Bp, T);
        } else {
            snn_kernel2<0><<<blocks, threads>>>((const float4*)d_in[0],
                fc1_w, fc1_b, beta1, thr1, fc2_w, fc2_b, beta2, thr2,
                (float4*)d_out, Bp, T);
        }
    } else {
        const int blocks = (B + threads - 1) / threads;
        snn_kernel1<<<blocks, threads>>>((const float2*)d_in[0],
            fc1_w, fc1_b, beta1, thr1, fc2_w, fc2_b, beta2, thr2,
            (float2*)d_out, B, T);
    }
}

// round 7
// speedup vs baseline: 1.0645x; 1.0645x over previous
#include <cuda_runtime.h>
#include <cstddef>

// SNN: 2-2-2 spiking net, B=500k independent elements, T=32 steps.
// R3 (1 elem/thread, float2 stcs): 57.8us, DRAM 70.9%.
// R4 (2 elem/thread, float4):      67.6us — grid 977 vs ~888 concurrent CTAs
//                                  => 1.1 waves, huge straggler tail.
// R5: persistent grid-stride kernel, grid = 888 CTAs (6/SM * 148), float2
//     stores as in R3. No wave quantization, perfectly balanced finish.
//
// FP association mirrors XLA's lowering exactly (verified rel_err==0):
//   dot:  acc = fma(x1, w[j][1], rnd(x0 * w[j][0]));  bias: cur = acc + b[j]
//   mem:  ((beta*mem + cur) - reset) with separate rn ops
//
// Output layout: [spk1 | spk2 | mem2], each [T,B,2] float32.

template<int T_STEPS>
__global__ __launch_bounds__(256)
void snn_kernel_gs(const float2* __restrict__ x,
                   const float* __restrict__ fc1_w, const float* __restrict__ fc1_b,
                   const float* __restrict__ beta1, const float* __restrict__ thr1,
                   const float* __restrict__ fc2_w, const float* __restrict__ fc2_b,
                   const float* __restrict__ beta2, const float* __restrict__ thr2,
                   float2* __restrict__ out, int B, int T_dyn)
{
    // Uniform broadcast params — load once per thread.
    const float w1_00 = __ldg(fc1_w + 0), w1_01 = __ldg(fc1_w + 1);
    const float w1_10 = __ldg(fc1_w + 2), w1_11 = __ldg(fc1_w + 3);
    const float b1_0  = __ldg(fc1_b + 0), b1_1  = __ldg(fc1_b + 1);
    const float w2_00 = __ldg(fc2_w + 0), w2_01 = __ldg(fc2_w + 1);
    const float w2_10 = __ldg(fc2_w + 2), w2_11 = __ldg(fc2_w + 3);
    const float b2_0  = __ldg(fc2_b + 0), b2_1  = __ldg(fc2_b + 1);
    const float bt1   = fminf(fmaxf(__ldg(beta1), 0.f), 1.f);
    const float bt2   = fminf(fmaxf(__ldg(beta2), 0.f), 1.f);
    const float th1   = __ldg(thr1);
    const float th2   = __ldg(thr2);

    const int T = (T_STEPS > 0) ? T_STEPS : T_dyn;
    const size_t TB = (size_t)T * (size_t)B;
    float2* __restrict__ o_spk1 = out;
    float2* __restrict__ o_spk2 = out + TB;
    float2* __restrict__ o_mem2 = out + 2 * TB;

    const int stride = gridDim.x * blockDim.x;

    for (int b = blockIdx.x * blockDim.x + threadIdx.x; b < B; b += stride) {
        const float2 xv = __ldg(&x[b]);
        const float cur1_0 = __fadd_rn(__fmaf_rn(xv.y, w1_01, __fmul_rn(xv.x, w1_00)), b1_0);
        const float cur1_1 = __fadd_rn(__fmaf_rn(xv.y, w1_11, __fmul_rn(xv.x, w1_10)), b1_1);

        float mem1_0 = 0.f, mem1_1 = 0.f, mem2_0 = 0.f, mem2_1 = 0.f;

#pragma unroll
        for (int t = 0; t < T; t++) {
            const float r1_0 = (mem1_0 > th1) ? th1 : 0.f;
            const float r1_1 = (mem1_1 > th1) ? th1 : 0.f;
            mem1_0 = __fsub_rn(__fadd_rn(__fmul_rn(bt1, mem1_0), cur1_0), r1_0);
            mem1_1 = __fsub_rn(__fadd_rn(__fmul_rn(bt1, mem1_1), cur1_1), r1_1);
            const float s1_0 = (mem1_0 > th1) ? 1.f : 0.f;
            const float s1_1 = (mem1_1 > th1) ? 1.f : 0.f;

            const float cur2_0 = __fadd_rn(__fmaf_rn(s1_1, w2_01, __fmul_rn(s1_0, w2_00)), b2_0);
            const float cur2_1 = __fadd_rn(__fmaf_rn(s1_1, w2_11, __fmul_rn(s1_0, w2_10)), b2_1);

            const float r2_0 = (mem2_0 > th2) ? th2 : 0.f;
            const float r2_1 = (mem2_1 > th2) ? th2 : 0.f;
            mem2_0 = __fsub_rn(__fadd_rn(__fmul_rn(bt2, mem2_0), cur2_0), r2_0);
            mem2_1 = __fsub_rn(__fadd_rn(__fmul_rn(bt2, mem2_1), cur2_1), r2_1);
            const float s2_0 = (mem2_0 > th2) ? 1.f : 0.f;
            const float s2_1 = (mem2_1 > th2) ? 1.f : 0.f;

            const size_t idx = (size_t)t * (size_t)B + (size_t)b;
            __stcs(&o_spk1[idx], make_float2(s1_0, s1_1));
            __stcs(&o_spk2[idx], make_float2(s2_0, s2_1));
            __stcs(&o_mem2[idx], make_float2(mem2_0, mem2_1));
        }
    }
}

extern "C" void kernel_launch(void* const* d_in, const int* in_sizes, int n_in,
                              void* d_out, int out_size) {
    const float2* x     = (const float2*)d_in[0];
    const float*  fc1_w = (const float*)d_in[1];
    const float*  fc1_b = (const float*)d_in[2];
    const float*  beta1 = (const float*)d_in[3];
    const float*  thr1  = (const float*)d_in[4];
    const float*  fc2_w = (const float*)d_in[5];
    const float*  fc2_b = (const float*)d_in[6];
    const float*  beta2 = (const float*)d_in[7];
    const float*  thr2  = (const float*)d_in[8];

    const int B = in_sizes[0] / 2;          // x is [B, 2]
    const int T = out_size / (6 * B);       // out = 3 arrays of [T, B, 2]

    const int threads = 256;
    // Persistent-style: ~6 CTAs/SM * 148 SMs = 888 CTAs, grid-stride over B.
    int blocks = 148 * 6;
    const int max_blocks = (B + threads - 1) / threads;
    if (blocks > max_blocks) blocks = max_blocks;

    if (T == 32) {
        snn_kernel_gs<32><<<blocks, threads>>>(x, fc1_w, fc1_b, beta1, thr1,
                                               fc2_w, fc2_b, beta2, thr2,
                                               (float2*)d_out, B, T);
    } else {
        snn_kernel_gs<0><<<blocks, threads>>>(x, fc1_w, fc1_b, beta1, thr1,
                                              fc2_w, fc2_b, beta2, thr2,
                                              (float2*)d_out, B, T);
    }
}

// round 8
// speedup vs baseline: 1.0919x; 1.0258x over previous
#include <cuda_runtime.h>
#include <cstddef>

// SNN: 2-2-2 spiking net, B=500k independent elements, T=32 steps.
// History: R3 (1 elem/thread) 57.8us DRAM 70.9%; R4 (pairs, 977 CTAs) 67.6us
// (1.1-wave tail); R5 (grid-stride 888) 63.6us (ceil-quantization eff 73%).
// Measured DRAM% tracks work-balance efficiency x ~87%. Fix: shrink the work
// quantum. Each work item = (element b, chunk c): recompute the recurrence
// (bit-identical, cheap) through 8*c silent steps, then store 8 timesteps.
// 4*B = 2M items -> 6.6 waves over ~1184 resident CTAs -> tail ~6%.
// Heavy chunks (c=3) are scheduled first (LPT) so the last wave is cheap.
//
// FP association mirrors XLA exactly (verified rel_err==0):
//   dot:  acc = fma(x1, w[j][1], rnd(x0*w[j][0]));  bias: cur = acc + b[j]
//   mem:  ((beta*mem + cur) - reset) with separate rn ops
//
// Output layout: [spk1 | spk2 | mem2], each [T,B,2] float32.

#define SNN_STEP()                                                              \
    do {                                                                        \
        const float r1_0 = (mem1_0 > th1) ? th1 : 0.f;                          \
        const float r1_1 = (mem1_1 > th1) ? th1 : 0.f;                          \
        mem1_0 = __fsub_rn(__fadd_rn(__fmul_rn(bt1, mem1_0), cur1_0), r1_0);    \
        mem1_1 = __fsub_rn(__fadd_rn(__fmul_rn(bt1, mem1_1), cur1_1), r1_1);    \
        s1_0 = (mem1_0 > th1) ? 1.f : 0.f;                                      \
        s1_1 = (mem1_1 > th1) ? 1.f : 0.f;                                      \
        const float cur2_0 =                                                    \
            __fadd_rn(__fmaf_rn(s1_1, w2_01, __fmul_rn(s1_0, w2_00)), b2_0);    \
        const float cur2_1 =                                                    \
            __fadd_rn(__fmaf_rn(s1_1, w2_11, __fmul_rn(s1_0, w2_10)), b2_1);    \
        const float r2_0 = (mem2_0 > th2) ? th2 : 0.f;                          \
        const float r2_1 = (mem2_1 > th2) ? th2 : 0.f;                          \
        mem2_0 = __fsub_rn(__fadd_rn(__fmul_rn(bt2, mem2_0), cur2_0), r2_0);    \
        mem2_1 = __fsub_rn(__fadd_rn(__fmul_rn(bt2, mem2_1), cur2_1), r2_1);    \
        s2_0 = (mem2_0 > th2) ? 1.f : 0.f;                                      \
        s2_1 = (mem2_1 > th2) ? 1.f : 0.f;                                      \
    } while (0)

// T=32 specialization, chunked: item = (b, c), store steps [8c, 8c+8).
__global__ __launch_bounds__(256, 8)
void snn_chunked32(const float2* __restrict__ x,
                   const float* __restrict__ fc1_w, const float* __restrict__ fc1_b,
                   const float* __restrict__ beta1, const float* __restrict__ thr1,
                   const float* __restrict__ fc2_w, const float* __restrict__ fc2_b,
                   const float* __restrict__ beta2, const float* __restrict__ thr2,
                   float2* __restrict__ out, int B)
{
    const int gid = blockIdx.x * blockDim.x + threadIdx.x;
    if (gid >= 4 * B) return;

    const int q = gid / B;          // 0..3, uniform within (almost) every warp
    const int b = gid - q * B;
    const int c = 3 - q;            // heavy chunks (c=3, most recompute) first

    const float w1_00 = __ldg(fc1_w + 0), w1_01 = __ldg(fc1_w + 1);
    const float w1_10 = __ldg(fc1_w + 2), w1_11 = __ldg(fc1_w + 3);
    const float b1_0  = __ldg(fc1_b + 0), b1_1  = __ldg(fc1_b + 1);
    const float w2_00 = __ldg(fc2_w + 0), w2_01 = __ldg(fc2_w + 1);
    const float w2_10 = __ldg(fc2_w + 2), w2_11 = __ldg(fc2_w + 3);
    const float b2_0  = __ldg(fc2_b + 0), b2_1  = __ldg(fc2_b + 1);
    const float bt1   = fminf(fmaxf(__ldg(beta1), 0.f), 1.f);
    const float bt2   = fminf(fmaxf(__ldg(beta2), 0.f), 1.f);
    const float th1   = __ldg(thr1);
    const float th2   = __ldg(thr2);

    const float2 xv = __ldg(&x[b]);
    const float cur1_0 = __fadd_rn(__fmaf_rn(xv.y, w1_01, __fmul_rn(xv.x, w1_00)), b1_0);
    const float cur1_1 = __fadd_rn(__fmaf_rn(xv.y, w1_11, __fmul_rn(xv.x, w1_10)), b1_1);

    float mem1_0 = 0.f, mem1_1 = 0.f, mem2_0 = 0.f, mem2_1 = 0.f;
    float s1_0, s1_1, s2_0, s2_1;

    // Silent recompute: 8*c steps (bit-identical to the stored path).
    for (int k = 0; k < c; k++) {
#pragma unroll
        for (int tt = 0; tt < 8; tt++) { SNN_STEP(); }
    }

    // Store phase: 8 steps at t = 8c + tt.
    const int TB = 32 * B;     // float2 elements per output array (16M < 2^31)
    float2* __restrict__ o_spk1 = out;
    float2* __restrict__ o_spk2 = out + TB;
    float2* __restrict__ o_mem2 = out + 2 * (size_t)TB;

    int idx = (c * 8) * B + b;
#pragma unroll
    for (int tt = 0; tt < 8; tt++) {
        SNN_STEP();
        __stcs(&o_spk1[idx], make_float2(s1_0, s1_1));
        __stcs(&o_spk2[idx], make_float2(s2_0, s2_1));
        __stcs(&o_mem2[idx], make_float2(mem2_0, mem2_1));
        idx += B;
    }
}

// Generic fallback: one element per thread, any T.
__global__ __launch_bounds__(256)
void snn_generic(const float2* __restrict__ x,
                 const float* __restrict__ fc1_w, const float* __restrict__ fc1_b,
                 const float* __restrict__ beta1, const float* __restrict__ thr1,
                 const float* __restrict__ fc2_w, const float* __restrict__ fc2_b,
                 const float* __restrict__ beta2, const float* __restrict__ thr2,
                 float2* __restrict__ out, int B, int T)
{
    const int b = blockIdx.x * blockDim.x + threadIdx.x;
    if (b >= B) return;

    const float w1_00 = __ldg(fc1_w + 0), w1_01 = __ldg(fc1_w + 1);
    const float w1_10 = __ldg(fc1_w + 2), w1_11 = __ldg(fc1_w + 3);
    const float b1_0  = __ldg(fc1_b + 0), b1_1  = __ldg(fc1_b + 1);
    const float w2_00 = __ldg(fc2_w + 0), w2_01 = __ldg(fc2_w + 1);
    const float w2_10 = __ldg(fc2_w + 2), w2_11 = __ldg(fc2_w + 3);
    const float b2_0  = __ldg(fc2_b + 0), b2_1  = __ldg(fc2_b + 1);
    const float bt1   = fminf(fmaxf(__ldg(beta1), 0.f), 1.f);
    const float bt2   = fminf(fmaxf(__ldg(beta2), 0.f), 1.f);
    const float th1   = __ldg(thr1);
    const float th2   = __ldg(thr2);

    const float2 xv = __ldg(&x[b]);
    const float cur1_0 = __fadd_rn(__fmaf_rn(xv.y, w1_01, __fmul_rn(xv.x, w1_00)), b1_0);
    const float cur1_1 = __fadd_rn(__fmaf_rn(xv.y, w1_11, __fmul_rn(xv.x, w1_10)), b1_1);

    float mem1_0 = 0.f, mem1_1 = 0.f, mem2_0 = 0.f, mem2_1 = 0.f;
    float s1_0, s1_1, s2_0, s2_1;

    const size_t TB = (size_t)T * (size_t)B;
    float2* __restrict__ o_spk1 = out;
    float2* __restrict__ o_spk2 = out + TB;
    float2* __restrict__ o_mem2 = out + 2 * TB;

    for (int t = 0; t < T; t++) {
        SNN_STEP();
        const size_t idx = (size_t)t * (size_t)B + (size_t)b;
        __stcs(&o_spk1[idx], make_float2(s1_0, s1_1));
        __stcs(&o_spk2[idx], make_float2(s2_0, s2_1));
        __stcs(&o_mem2[idx], make_float2(mem2_0, mem2_1));
    }
}

extern "C" void kernel_launch(void* const* d_in, const int* in_sizes, int n_in,
                              void* d_out, int out_size) {
    const float2* x     = (const float2*)d_in[0];
    const float*  fc1_w = (const float*)d_in[1];
    const float*  fc1_b = (const float*)d_in[2];
    const float*  beta1 = (const float*)d_in[3];
    const float*  thr1  = (const float*)d_in[4];
    const float*  fc2_w = (const float*)d_in[5];
    const float*  fc2_b = (const float*)d_in[6];
    const float*  beta2 = (const float*)d_in[7];
    const float*  thr2  = (const float*)d_in[8];

    const int B = in_sizes[0] / 2;          // x is [B, 2]
    const int T = out_size / (6 * B);       // out = 3 arrays of [T, B, 2]

    const int threads = 256;

    if (T == 32) {
        const long long items = 4LL * B;    // (element, 8-step chunk)
        const int blocks = (int)((items + threads - 1) / threads);
        snn_chunked32<<<blocks, threads>>>(x, fc1_w, fc1_b, beta1, thr1,
                                           fc2_w, fc2_b, beta2, thr2,
                                           (float2*)d_out, B);
    } else {
        const int blocks = (B + threads - 1) / threads;
        snn_generic<<<blocks, threads>>>(x, fc1_w, fc1_b, beta1, thr1,
                                         fc2_w, fc2_b, beta2, thr2,
                                         (float2*)d_out, B, T);
    }
}

// round 9
// speedup vs baseline: 1.1251x; 1.0303x over previous
#include <cuda_runtime.h>
#include <cstddef>

// SNN: 2-2-2 spiking net, B=500k independent elements, T=32 steps.
// History:
//   R3: 1 elem/thread, float2 stcs        57.8us  DRAM 70.9%  issue 31%
//   R4: pairs/float4, 977 CTAs            67.6us  (1.1-wave tail)
//   R5: grid-stride 888                   63.6us  (quantization eff 73%)
//   R8: 4x8-step chunks                   62.0us  DRAM 67.8%  issue 66% (!)
// Model: dur = max(store_floor / wave_balance, issue_time).
// R9: 2 chunks of 16 steps (items=2B -> 4.4 waves, balance ~88%), recompute
// only for chunk 1 (compute = 1.5x R3 -> issue ~45%), LPT heavy-chunk-first,
// and reset/spike comparison reuse (reset at t == spike at t-1, carried).
//
// FP association mirrors XLA exactly (verified rel_err==0):
//   dot:  acc = fma(x1, w[j][1], rnd(x0*w[j][0]));  bias: cur = acc + b[j]
//   mem:  ((beta*mem + cur) - reset) with separate rn ops
//   reset = s_prev ? th : 0   (s_prev in {0,1}; select is exact)
//
// Output layout: [spk1 | spk2 | mem2], each [T,B,2] float32.

#define SNN_STEP()                                                              \
    do {                                                                        \
        const float r1_0 = s1_0 != 0.f ? th1 : 0.f;                             \
        const float r1_1 = s1_1 != 0.f ? th1 : 0.f;                             \
        mem1_0 = __fsub_rn(__fadd_rn(__fmul_rn(bt1, mem1_0), cur1_0), r1_0);    \
        mem1_1 = __fsub_rn(__fadd_rn(__fmul_rn(bt1, mem1_1), cur1_1), r1_1);    \
        s1_0 = (mem1_0 > th1) ? 1.f : 0.f;                                      \
        s1_1 = (mem1_1 > th1) ? 1.f : 0.f;                                      \
        const float cur2_0 =                                                    \
            __fadd_rn(__fmaf_rn(s1_1, w2_01, __fmul_rn(s1_0, w2_00)), b2_0);    \
        const float cur2_1 =                                                    \
            __fadd_rn(__fmaf_rn(s1_1, w2_11, __fmul_rn(s1_0, w2_10)), b2_1);    \
        const float r2_0 = s2_0 != 0.f ? th2 : 0.f;                             \
        const float r2_1 = s2_1 != 0.f ? th2 : 0.f;                             \
        mem2_0 = __fsub_rn(__fadd_rn(__fmul_rn(bt2, mem2_0), cur2_0), r2_0);    \
        mem2_1 = __fsub_rn(__fadd_rn(__fmul_rn(bt2, mem2_1), cur2_1), r2_1);    \
        s2_0 = (mem2_0 > th2) ? 1.f : 0.f;                                      \
        s2_1 = (mem2_1 > th2) ? 1.f : 0.f;                                      \
    } while (0)

#define SNN_LOAD_PARAMS()                                                       \
    const float w1_00 = __ldg(fc1_w + 0), w1_01 = __ldg(fc1_w + 1);             \
    const float w1_10 = __ldg(fc1_w + 2), w1_11 = __ldg(fc1_w + 3);             \
    const float b1_0  = __ldg(fc1_b + 0), b1_1  = __ldg(fc1_b + 1);             \
    const float w2_00 = __ldg(fc2_w + 0), w2_01 = __ldg(fc2_w + 1);             \
    const float w2_10 = __ldg(fc2_w + 2), w2_11 = __ldg(fc2_w + 3);             \
    const float b2_0  = __ldg(fc2_b + 0), b2_1  = __ldg(fc2_b + 1);             \
    const float bt1   = fminf(fmaxf(__ldg(beta1), 0.f), 1.f);                   \
    const float bt2   = fminf(fmaxf(__ldg(beta2), 0.f), 1.f);                   \
    const float th1   = __ldg(thr1);                                            \
    const float th2   = __ldg(thr2)

// T=32: item = (element b, 16-step half). Heavy half (c=1) scheduled first.
__global__ __launch_bounds__(256, 8)
void snn_half32(const float2* __restrict__ x,
                const float* __restrict__ fc1_w, const float* __restrict__ fc1_b,
                const float* __restrict__ beta1, const float* __restrict__ thr1,
                const float* __restrict__ fc2_w, const float* __restrict__ fc2_b,
                const float* __restrict__ beta2, const float* __restrict__ thr2,
                float2* __restrict__ out, int B)
{
    const int gid = blockIdx.x * blockDim.x + threadIdx.x;
    if (gid >= 2 * B) return;

    // LPT: gid < B -> chunk 1 (16 silent + 16 stored); else chunk 0.
    const bool heavy = (gid < B);
    const int b = heavy ? gid : gid - B;
    const int c = heavy ? 1 : 0;

    SNN_LOAD_PARAMS();

    const float2 xv = __ldg(&x[b]);
    const float cur1_0 = __fadd_rn(__fmaf_rn(xv.y, w1_01, __fmul_rn(xv.x, w1_00)), b1_0);
    const float cur1_1 = __fadd_rn(__fmaf_rn(xv.y, w1_11, __fmul_rn(xv.x, w1_10)), b1_1);

    float mem1_0 = 0.f, mem1_1 = 0.f, mem2_0 = 0.f, mem2_1 = 0.f;
    // Initial "previous spike" = Heaviside(0 - th): matches reference's
    // reset computed from mem=0 at t=0.
    float s1_0 = (0.f > th1) ? 1.f : 0.f;
    float s1_1 = s1_0;
    float s2_0 = (0.f > th2) ? 1.f : 0.f;
    float s2_1 = s2_0;

    if (c) {
#pragma unroll
        for (int tt = 0; tt < 16; tt++) { SNN_STEP(); }
    }

    const int TB = 32 * B;
    float2* __restrict__ o_spk1 = out;
    float2* __restrict__ o_spk2 = out + TB;
    float2* __restrict__ o_mem2 = out + 2 * (size_t)TB;

    int idx = (c * 16) * B + b;
#pragma unroll
    for (int tt = 0; tt < 16; tt++) {
        SNN_STEP();
        __stcs(&o_spk1[idx], make_float2(s1_0, s1_1));
        __stcs(&o_spk2[idx], make_float2(s2_0, s2_1));
        __stcs(&o_mem2[idx], make_float2(mem2_0, mem2_1));
        idx += B;
    }
}

// Generic fallback: one element per thread, any T.
__global__ __launch_bounds__(256)
void snn_generic(const float2* __restrict__ x,
                 const float* __restrict__ fc1_w, const float* __restrict__ fc1_b,
                 const float* __restrict__ beta1, const float* __restrict__ thr1,
                 const float* __restrict__ fc2_w, const float* __restrict__ fc2_b,
                 const float* __restrict__ beta2, const float* __restrict__ thr2,
                 float2* __restrict__ out, int B, int T)
{
    const int b = blockIdx.x * blockDim.x + threadIdx.x;
    if (b >= B) return;

    SNN_LOAD_PARAMS();

    const float2 xv = __ldg(&x[b]);
    const float cur1_0 = __fadd_rn(__fmaf_rn(xv.y, w1_01, __fmul_rn(xv.x, w1_00)), b1_0);
    const float cur1_1 = __fadd_rn(__fmaf_rn(xv.y, w1_11, __fmul_rn(xv.x, w1_10)), b1_1);

    float mem1_0 = 0.f, mem1_1 = 0.f, mem2_0 = 0.f, mem2_1 = 0.f;
    float s1_0 = (0.f > th1) ? 1.f : 0.f;
    float s1_1 = s1_0;
    float s2_0 = (0.f > th2) ? 1.f : 0.f;
    float s2_1 = s2_0;

    const size_t TB = (size_t)T * (size_t)B;
    float2* __restrict__ o_spk1 = out;
    float2* __restrict__ o_spk2 = out + TB;
    float2* __restrict__ o_mem2 = out + 2 * TB;

    for (int t = 0; t < T; t++) {
        SNN_STEP();
        const size_t idx = (size_t)t * (size_t)B + (size_t)b;
        __stcs(&o_spk1[idx], make_float2(s1_0, s1_1));
        __stcs(&o_spk2[idx], make_float2(s2_0, s2_1));
        __stcs(&o_mem2[idx], make_float2(mem2_0, mem2_1));
    }
}

extern "C" void kernel_launch(void* const* d_in, const int* in_sizes, int n_in,
                              void* d_out, int out_size) {
    const float2* x     = (const float2*)d_in[0];
    const float*  fc1_w = (const float*)d_in[1];
    const float*  fc1_b = (const float*)d_in[2];
    const float*  beta1 = (const float*)d_in[3];
    const float*  thr1  = (const float*)d_in[4];
    const float*  fc2_w = (const float*)d_in[5];
    const float*  fc2_b = (const float*)d_in[6];
    const float*  beta2 = (const float*)d_in[7];
    const float*  thr2  = (const float*)d_in[8];

    const int B = in_sizes[0] / 2;          // x is [B, 2]
    const int T = out_size / (6 * B);       // out = 3 arrays of [T, B, 2]

    const int threads = 256;

    if (T == 32) {
        const long long items = 2LL * B;    // (element, 16-step half)
        const int blocks = (int)((items + threads - 1) / threads);
        snn_half32<<<blocks, threads>>>(x, fc1_w, fc1_b, beta1, thr1,
                                        fc2_w, fc2_b, beta2, thr2,
                                        (float2*)d_out, B);
    } else {
        const int blocks = (B + threads - 1) / threads;
        snn_generic<<<blocks, threads>>>(x, fc1_w, fc1_b, beta1, thr1,
                                         fc2_w, fc2_b, beta2, thr2,
                                         (float2*)d_out, B, T);
    }
}